// round 10
// baseline (speedup 1.0000x reference)
#include <cuda_runtime.h>
#include <cuda_bf16.h>
#include <cstdint>

// Problem shape (fixed by the reference)
#define BB 8
#define CC 16
#define HH 512
#define WW 1024
#define CPB 8                       // channels per block
#define CSTRIDE (HH * WW)           // 524288

// Block = one (b,h) row x 8 channels (grid = 8192).
// Phase 1: stage the 8 channel-rows (32KB) into smem with perfectly
//          sequential coalesced float4 loads -> DRAM sees a pure read stream.
// Phase 2: bilinear gather out of smem. Pixel->thread map is stride-256
//          (thread t owns pixels t, t+256, t+512, t+768) so warp lanes hit
//          consecutive smem words: conflict-free LDS, coalesced STG.32.
// Rationale (R4/R5/R7/R9 evidence): traffic is minimal and neither occupancy,
// L1 wavefronts, nor L2 policy move the ~5.5TB/s plateau; the one untested
// factor is gather-shaped read requests capping DRAM stream efficiency.
__global__ __launch_bounds__(256) void warp_disp_kernel(
    const float* __restrict__ input,   // [B,C,H,W]
    const float* __restrict__ disp,    // [B,1,H,W]
    float* __restrict__ out)           // [B,C,H,W]
{
    __shared__ float srow[CPB * WW];   // 32 KB

    const int bh = blockIdx.x >> 1;    // b*H + h, 0..4095
    const int cg = blockIdx.x & 1;     // channel group: channels [cg*8, cg*8+8)
    const int h  = bh & (HH - 1);
    const int b  = bh >> 9;            // /HH
    const int t  = threadIdx.x;

    // base element offset of channel cg*8, row (b,h); fits in int32 (<64M)
    const int base = (b * CC * HH + h) * WW + cg * CPB * CSTRIDE;

    // ---- Phase 1: stage 8 channel-rows, fully coalesced float4 stream ----
    #pragma unroll
    for (int c = 0; c < CPB; ++c) {
        const float4 v = __ldg((const float4*)(input + base + c * CSTRIDE) + t);
        *(float4*)(srow + c * WW + t * 4) = v;
    }

    // ---- per-pixel indices/weights (independent of channels) ----
    const float* drow = disp + bh * WW;
    int   x0[4], x1[4];
    float wl[4], wr[4];
    #pragma unroll
    for (int j = 0; j < 4; ++j) {
        const int w = t + j * 256;
        float x = (float)w + __ldg(drow + w);     // coalesced
        x = fminf(fmaxf(x, 0.0f), (float)(WW - 1));
        const float x0f = floorf(x);
        const float x1f = fminf(x0f + 1.0f, (float)(WW - 1));
        x0[j] = (int)x0f;
        x1[j] = (int)x1f;
        wl[j] = x1f - x;          // note: NOT 1-wr; both 0 at the right clamp
        wr[j] = x - x0f;
    }

    __syncthreads();

    // ---- Phase 2: gather from smem (conflict-free), coalesced stores ----
    #pragma unroll
    for (int c = 0; c < CPB; ++c) {
        const float* s  = srow + c * WW;
        float*       oc = out + base + c * CSTRIDE;
        #pragma unroll
        for (int j = 0; j < 4; ++j) {
            oc[t + j * 256] = wl[j] * s[x0[j]] + wr[j] * s[x1[j]];
        }
    }
}

extern "C" void kernel_launch(void* const* d_in, const int* in_sizes, int n_in,
                              void* d_out, int out_size) {
    const float* input = (const float*)d_in[0];
    const float* disp  = (const float*)d_in[1];
    float* out = (float*)d_out;

    warp_disp_kernel<<<BB * HH * 2, 256>>>(input, disp, out);   // 8192 blocks
}

// round 11
// speedup vs baseline: 1.1052x; 1.1052x over previous
#include <cuda_runtime.h>
#include <cuda_bf16.h>
#include <cstdint>

// Problem shape (fixed by the reference)
#define BB 8
#define CC 16
#define HH 512
#define WW 1024

// FINAL configuration — the measured optimum across 6 profiled variants.
// One thread = 4 consecutive-w pixels; disp/index/weight computed once and
// shared across all 16 channels; per channel-iter: 8 batched scalar gathers
// (default caching — x0/x1 line reuse matters, R7 proved .cs hints cost 20us)
// + one aligned float4 store. No occupancy cap (R5: occ is not the limiter),
// no smem staging (R10: pure-stream reads don't raise DRAM%), no stride-256
// remap (R9: fewer L1 wavefronts don't either). The kernel runs at the chip's
// practical ~5.6TB/s ceiling for a 1:1 read:write HBM stream mix.
__global__ __launch_bounds__(256) void warp_disp_kernel(
    const float* __restrict__ input,   // [B,C,H,W]
    const float* __restrict__ disp,    // [B,1,H,W]
    float* __restrict__ out)           // [B,C,H,W]
{
    const int tid = blockIdx.x * blockDim.x + threadIdx.x;   // 1M threads
    const int w0  = (tid * 4) & (WW - 1);                    // 0..1020, step 4
    const int bh  = tid / (WW / 4);                          // b*H + h
    const int h   = bh & (HH - 1);
    const int b   = bh >> 9;                                 // /HH

    // disp layout [B,1,H,W] == [B*H*W]; aligned float4 load
    const float4 d4 = __ldg((const float4*)(disp + bh * WW + w0));

    int   x0[4], x1[4];
    float wl[4], wr[4];
    const float dvals[4] = {d4.x, d4.y, d4.z, d4.w};
    #pragma unroll
    for (int i = 0; i < 4; ++i) {
        float x = (float)(w0 + i) + dvals[i];
        x = fminf(fmaxf(x, 0.0f), (float)(WW - 1));
        const float x0f = floorf(x);
        const float x1f = fminf(x0f + 1.0f, (float)(WW - 1));
        x0[i] = (int)x0f;
        x1[i] = (int)x1f;
        wl[i] = x1f - x;          // note: NOT 1-wr; both 0 at the right clamp
        wr[i] = x - x0f;
    }

    // All element offsets fit in int32 (64M elements max).
    const int row_base = (b * CC * HH + h) * WW;
    const float* in_row = input + row_base;
    float*      out_row = out   + row_base + w0;
    const int cstride = HH * WW;   // 524288

    #pragma unroll 4
    for (int c = 0; c < CC; ++c) {
        const float* rc = in_row + c * cstride;
        // Batch all 8 gathers ahead of the FMA/store chain (max MLP per iter).
        const float pl0 = __ldg(rc + x0[0]);
        const float pr0 = __ldg(rc + x1[0]);
        const float pl1 = __ldg(rc + x0[1]);
        const float pr1 = __ldg(rc + x1[1]);
        const float pl2 = __ldg(rc + x0[2]);
        const float pr2 = __ldg(rc + x1[2]);
        const float pl3 = __ldg(rc + x0[3]);
        const float pr3 = __ldg(rc + x1[3]);
        float4 r;
        r.x = wl[0] * pl0 + wr[0] * pr0;
        r.y = wl[1] * pl1 + wr[1] * pr1;
        r.z = wl[2] * pl2 + wr[2] * pr2;
        r.w = wl[3] * pl3 + wr[3] * pr3;
        *(float4*)(out_row + c * cstride) = r;
    }
}

extern "C" void kernel_launch(void* const* d_in, const int* in_sizes, int n_in,
                              void* d_out, int out_size) {
    const float* input = (const float*)d_in[0];
    const float* disp  = (const float*)d_in[1];
    float* out = (float*)d_out;

    const int n_threads = BB * HH * (WW / 4);   // 1,048,576
    const int threads = 256;
    warp_disp_kernel<<<n_threads / threads, threads>>>(input, disp, out);
}